// round 3
// baseline (speedup 1.0000x reference)
#include <cuda_runtime.h>
#include <cuda_bf16.h>
#include <math.h>

// Problem constants
#define BATCH   2
#define TSEQ    2048
#define EMBED   1024
#define NHEAD   16
#define HDIM    64
#define MTOK    (BATCH * TSEQ)        // 4096
#define QKVCOLS (3 * EMBED)           // 3072

// Scratch (allocation-free rule: __device__ globals)
__device__ float g_qkv[(size_t)MTOK * QKVCOLS];   // [4096, 3072]
__device__ float g_att[(size_t)MTOK * EMBED];     // [4096, 1024]

// ---------------------------------------------------------------------------
// SGEMM: C[M,N] = A[M,K] @ B[K,N] + bias[N]
// 128x128 block tile, BK=8, 256 threads, 8x8 per thread (split 4+4).
// Requires M%128==0, N%128==0, K%8==0 (true for all our shapes).
// ---------------------------------------------------------------------------
__global__ __launch_bounds__(256) void sgemm_bias_kernel(
    const float* __restrict__ A, const float* __restrict__ Bm,
    const float* __restrict__ bias, float* __restrict__ C,
    int M, int N, int K)
{
    const int BM = 128, BN = 128, BK = 8;
    __shared__ float As[BK][BM];   // transposed: [k][m]
    __shared__ float Bs[BK][BN];   // [k][n]

    const int tid = threadIdx.x;
    const int tx  = tid & 15;      // 0..15 (n dir)
    const int ty  = tid >> 4;      // 0..15 (m dir)
    const int bm  = blockIdx.y * BM;
    const int bn  = blockIdx.x * BN;

    // Global load assignments
    const int arow = tid >> 1;            // 0..127
    const int aseg = (tid & 1) * 4;       // 0 or 4 (k offset)
    const int brow = tid >> 5;            // 0..7   (k)
    const int bcol = (tid & 31) * 4;      // 0..124 (n)

    const float* Aptr = A + (size_t)(bm + arow) * K + aseg;
    const float* Bptr = Bm + (size_t)brow * N + bn + bcol;

    float acc[8][8];
    #pragma unroll
    for (int i = 0; i < 8; i++)
        #pragma unroll
        for (int j = 0; j < 8; j++) acc[i][j] = 0.0f;

    for (int k0 = 0; k0 < K; k0 += BK) {
        float4 a4 = *(const float4*)(Aptr + k0);
        float4 b4 = *(const float4*)(Bptr + (size_t)k0 * N);
        As[aseg + 0][arow] = a4.x;
        As[aseg + 1][arow] = a4.y;
        As[aseg + 2][arow] = a4.z;
        As[aseg + 3][arow] = a4.w;
        *(float4*)&Bs[brow][bcol] = b4;
        __syncthreads();

        #pragma unroll
        for (int k = 0; k < BK; k++) {
            float ar[8], br[8];
            *(float4*)&ar[0] = *(const float4*)&As[k][ty * 4];
            *(float4*)&ar[4] = *(const float4*)&As[k][64 + ty * 4];
            *(float4*)&br[0] = *(const float4*)&Bs[k][tx * 4];
            *(float4*)&br[4] = *(const float4*)&Bs[k][64 + tx * 4];
            #pragma unroll
            for (int i = 0; i < 8; i++)
                #pragma unroll
                for (int j = 0; j < 8; j++)
                    acc[i][j] = fmaf(ar[i], br[j], acc[i][j]);
        }
        __syncthreads();
    }

    // Epilogue with bias
    #pragma unroll
    for (int i = 0; i < 8; i++) {
        int r = bm + ((i < 4) ? (ty * 4 + i) : (64 + ty * 4 + i - 4));
        #pragma unroll
        for (int js = 0; js < 2; js++) {
            int c = bn + js * 64 + tx * 4;
            float4 o;
            o.x = acc[i][js * 4 + 0] + bias[c + 0];
            o.y = acc[i][js * 4 + 1] + bias[c + 1];
            o.z = acc[i][js * 4 + 2] + bias[c + 2];
            o.w = acc[i][js * 4 + 3] + bias[c + 3];
            *(float4*)&C[(size_t)r * N + c] = o;
        }
    }
}

// ---------------------------------------------------------------------------
// Flash attention (fp32, causal). One CTA per (qtile=64 rows, head, batch).
// 256 threads = 16x16; thread (ty,tx) owns S rows ty*4..+3, cols tx*4..+3.
// smem: Qs (k-major), KP (K k-major, reused as P row-major), Vs (row-major).
// 3 * 64*64*4B = 48 KB static shared.
// ---------------------------------------------------------------------------
__global__ __launch_bounds__(256) void attn_kernel(
    const float* __restrict__ qkv, float* __restrict__ att)
{
    __shared__ float Qs[64][64];   // [k][r]  (Q transposed, pre-scaled)
    __shared__ float KP[64][64];   // K: [k][c] ; later P: [r][c]
    __shared__ float Vs[64][64];   // [c][d]

    const int tid = threadIdx.x;
    const int tx  = tid & 15;
    const int ty  = tid >> 4;
    const int qt  = blockIdx.x;          // 0..31
    const int h   = blockIdx.y;          // 0..15
    const int b   = blockIdx.z;          // 0..1
    const int q0  = qt * 64;

    const size_t rstride = QKVCOLS;      // 3072 floats per token row
    const float* qbase = qkv + (size_t)b * TSEQ * rstride + h * HDIM;
    const float* kbase = qbase + EMBED;
    const float* vbase = qbase + 2 * EMBED;

    const float scale = 0.125f;          // 1/sqrt(64)

    // Load Q tile (64x64) transposed + scaled
    #pragma unroll
    for (int i = 0; i < 4; i++) {
        int f4 = tid + i * 256;
        int r  = f4 >> 4;
        int c4 = (f4 & 15) * 4;
        float4 v = *(const float4*)(qbase + (size_t)(q0 + r) * rstride + c4);
        Qs[c4 + 0][r] = v.x * scale;
        Qs[c4 + 1][r] = v.y * scale;
        Qs[c4 + 2][r] = v.z * scale;
        Qs[c4 + 3][r] = v.w * scale;
    }

    float m[4], l[4], o[4][4];
    #pragma unroll
    for (int i = 0; i < 4; i++) {
        m[i] = -1e30f; l[i] = 0.0f;
        #pragma unroll
        for (int j = 0; j < 4; j++) o[i][j] = 0.0f;
    }

    const int nk = qt + 1;
    for (int kt = 0; kt < nk; kt++) {
        const int k0 = kt * 64;
        __syncthreads();  // prior P/V reads done before overwrite (also covers Qs on 1st iter... covered by next sync)

        // Load K transposed + V row-major
        #pragma unroll
        for (int i = 0; i < 4; i++) {
            int f4 = tid + i * 256;
            int r  = f4 >> 4;
            int c4 = (f4 & 15) * 4;
            float4 kv = *(const float4*)(kbase + (size_t)(k0 + r) * rstride + c4);
            KP[c4 + 0][r] = kv.x;
            KP[c4 + 1][r] = kv.y;
            KP[c4 + 2][r] = kv.z;
            KP[c4 + 3][r] = kv.w;
            float4 vv = *(const float4*)(vbase + (size_t)(k0 + r) * rstride + c4);
            *(float4*)&Vs[r][c4] = vv;
        }
        __syncthreads();

        // S = Q @ K^T (pre-scaled)
        float s[4][4];
        #pragma unroll
        for (int i = 0; i < 4; i++)
            #pragma unroll
            for (int j = 0; j < 4; j++) s[i][j] = 0.0f;

        #pragma unroll 8
        for (int k = 0; k < 64; k++) {
            float4 aq = *(const float4*)&Qs[k][ty * 4];
            float4 bk = *(const float4*)&KP[k][tx * 4];
            float ar[4] = {aq.x, aq.y, aq.z, aq.w};
            float br[4] = {bk.x, bk.y, bk.z, bk.w};
            #pragma unroll
            for (int i = 0; i < 4; i++)
                #pragma unroll
                for (int j = 0; j < 4; j++)
                    s[i][j] = fmaf(ar[i], br[j], s[i][j]);
        }

        // Causal mask on diagonal tile
        if (kt == qt) {
            #pragma unroll
            for (int i = 0; i < 4; i++) {
                int qg = q0 + ty * 4 + i;
                #pragma unroll
                for (int j = 0; j < 4; j++) {
                    int kg = k0 + tx * 4 + j;
                    if (kg > qg) s[i][j] = -1e30f;
                }
            }
        }

        // Online softmax (row stats across 16 tx lanes)
        #pragma unroll
        for (int i = 0; i < 4; i++) {
            float mx = s[i][0];
            mx = fmaxf(mx, s[i][1]);
            mx = fmaxf(mx, s[i][2]);
            mx = fmaxf(mx, s[i][3]);
            #pragma unroll
            for (int d = 1; d < 16; d <<= 1)
                mx = fmaxf(mx, __shfl_xor_sync(0xffffffffu, mx, d));
            float mnew = fmaxf(m[i], mx);
            float corr = __expf(m[i] - mnew);
            m[i] = mnew;
            float rs = 0.0f;
            #pragma unroll
            for (int j = 0; j < 4; j++) {
                float p = __expf(s[i][j] - mnew);
                s[i][j] = p;
                rs += p;
            }
            #pragma unroll
            for (int d = 1; d < 16; d <<= 1)
                rs += __shfl_xor_sync(0xffffffffu, rs, d);
            l[i] = l[i] * corr + rs;
            #pragma unroll
            for (int j = 0; j < 4; j++) o[i][j] *= corr;
        }

        __syncthreads();  // everyone done reading KP as K

        // Write P into KP (row-major [r][c])
        #pragma unroll
        for (int i = 0; i < 4; i++)
            #pragma unroll
            for (int j = 0; j < 4; j++)
                KP[ty * 4 + i][tx * 4 + j] = s[i][j];
        __syncthreads();

        // O += P @ V
        #pragma unroll 8
        for (int c = 0; c < 64; c++) {
            float pv0 = KP[ty * 4 + 0][c];
            float pv1 = KP[ty * 4 + 1][c];
            float pv2 = KP[ty * 4 + 2][c];
            float pv3 = KP[ty * 4 + 3][c];
            float4 vv = *(const float4*)&Vs[c][tx * 4];
            o[0][0] = fmaf(pv0, vv.x, o[0][0]); o[0][1] = fmaf(pv0, vv.y, o[0][1]);
            o[0][2] = fmaf(pv0, vv.z, o[0][2]); o[0][3] = fmaf(pv0, vv.w, o[0][3]);
            o[1][0] = fmaf(pv1, vv.x, o[1][0]); o[1][1] = fmaf(pv1, vv.y, o[1][1]);
            o[1][2] = fmaf(pv1, vv.z, o[1][2]); o[1][3] = fmaf(pv1, vv.w, o[1][3]);
            o[2][0] = fmaf(pv2, vv.x, o[2][0]); o[2][1] = fmaf(pv2, vv.y, o[2][1]);
            o[2][2] = fmaf(pv2, vv.z, o[2][2]); o[2][3] = fmaf(pv2, vv.w, o[2][3]);
            o[3][0] = fmaf(pv3, vv.x, o[3][0]); o[3][1] = fmaf(pv3, vv.y, o[3][1]);
            o[3][2] = fmaf(pv3, vv.z, o[3][2]); o[3][3] = fmaf(pv3, vv.w, o[3][3]);
        }
    }

    // Normalize and store: att[b*T + r][h*64 + d]
    #pragma unroll
    for (int i = 0; i < 4; i++) {
        float inv = 1.0f / l[i];
        int r = q0 + ty * 4 + i;
        float4 ov;
        ov.x = o[i][0] * inv;
        ov.y = o[i][1] * inv;
        ov.z = o[i][2] * inv;
        ov.w = o[i][3] * inv;
        *(float4*)&att[((size_t)(b * TSEQ + r)) * EMBED + h * HDIM + tx * 4] = ov;
    }
}

// ---------------------------------------------------------------------------
// Launch
// ---------------------------------------------------------------------------
extern "C" void kernel_launch(void* const* d_in, const int* in_sizes, int n_in,
                              void* d_out, int out_size)
{
    const float* x     = (const float*)d_in[0];   // [2,2048,1024]
    const float* w_qkv = (const float*)d_in[1];   // [1024,3072]
    const float* b_qkv = (const float*)d_in[2];   // [3072]
    const float* w_out = (const float*)d_in[3];   // [1024,1024]
    const float* b_out = (const float*)d_in[4];   // [1024]
    float* out = (float*)d_out;                   // [2,2048,1024]

    float* qkv_ptr = nullptr;
    float* att_ptr = nullptr;
    cudaGetSymbolAddress((void**)&qkv_ptr, g_qkv);
    cudaGetSymbolAddress((void**)&att_ptr, g_att);

    // 1) QKV projection: [4096,1024] @ [1024,3072]
    {
        dim3 grid(QKVCOLS / 128, MTOK / 128);
        sgemm_bias_kernel<<<grid, 256>>>(x, w_qkv, b_qkv, qkv_ptr,
                                         MTOK, QKVCOLS, EMBED);
    }

    // 2) Causal flash attention
    {
        dim3 grid(TSEQ / 64, NHEAD, BATCH);
        attn_kernel<<<grid, 256>>>(qkv_ptr, att_ptr);
    }

    // 3) Output projection: [4096,1024] @ [1024,1024]
    {
        dim3 grid(EMBED / 128, MTOK / 128);
        sgemm_bias_kernel<<<grid, 256>>>(att_ptr, w_out, b_out, out,
                                         MTOK, EMBED, EMBED);
    }
}